// round 2
// baseline (speedup 1.0000x reference)
#include <cuda_runtime.h>

// Reference analysis: the returned tensor is x.reshape(b,64,8,6,6).reshape(b,512,6,6)
// == x exactly. All other computation ('features', 'z') is deleted/dead.
// Optimal kernel = D2D copy of in[0] -> out (4096*512*6*6 fp32 = ~302 MB).

extern "C" void kernel_launch(void* const* d_in, const int* in_sizes, int n_in,
                              void* d_out, int out_size) {
    (void)n_in;
    size_t bytes = (size_t)out_size * sizeof(float);
    // in_sizes[0] should equal out_size; clamp defensively.
    size_t in_bytes = (size_t)in_sizes[0] * sizeof(float);
    if (in_bytes < bytes) bytes = in_bytes;
    cudaMemcpyAsync(d_out, d_in[0], bytes, cudaMemcpyDeviceToDevice, 0);
}

// round 3
// speedup vs baseline: 1.0266x; 1.0266x over previous
#include <cuda_runtime.h>
#include <cstdint>

// Output == input exactly (reference returns x reshaped; all other work is dead).
// Pure bandwidth problem: 302 MB read + 302 MB write.
// SM-side float4 streaming copy, 4 independent 16B loads per thread per iter
// for MLP, grid-stride to cover 18,874,368 float4 elements.

__global__ __launch_bounds__(256) void copy_kernel(const float4* __restrict__ src,
                                                   float4* __restrict__ dst,
                                                   long long n4) {
    long long i = (long long)blockIdx.x * (blockDim.x * 4) + threadIdx.x;
    long long stride = (long long)gridDim.x * blockDim.x * 4;
    for (; i + 3LL * blockDim.x < n4; i += stride) {
        // 4 independent loads front-batched (MLP), streaming hints (no reuse).
        float4 a = __ldcs(src + i);
        float4 b = __ldcs(src + i + blockDim.x);
        float4 c = __ldcs(src + i + 2 * blockDim.x);
        float4 d = __ldcs(src + i + 3 * blockDim.x);
        __stcs(dst + i, a);
        __stcs(dst + i + blockDim.x, b);
        __stcs(dst + i + 2 * blockDim.x, c);
        __stcs(dst + i + 3 * blockDim.x, d);
    }
    // tail
    for (; i < n4; i += (long long)blockDim.x) {
        if (i < n4) __stcs(dst + i, __ldcs(src + i));
    }
}

__global__ void copy_tail(const float* __restrict__ src, float* __restrict__ dst,
                          long long start, long long n) {
    long long i = start + blockIdx.x * blockDim.x + threadIdx.x;
    if (i < n) dst[i] = src[i];
}

extern "C" void kernel_launch(void* const* d_in, const int* in_sizes, int n_in,
                              void* d_out, int out_size) {
    (void)n_in;
    long long n = out_size;               // 75,497,472 floats
    long long n4 = n / 4;                 // 18,874,368 float4
    const int threads = 256;
    // ~4 float4 per thread per iter; pick grid so one grid-stride pass covers all.
    long long work_per_block = (long long)threads * 4;
    int blocks = (int)((n4 + work_per_block - 1) / work_per_block);
    if (blocks > 0)
        copy_kernel<<<blocks, threads>>>((const float4*)d_in[0], (float4*)d_out, n4);
    long long rem_start = n4 * 4;
    if (rem_start < n) {
        long long rem = n - rem_start;
        copy_tail<<<(int)((rem + 255) / 256), 256>>>((const float*)d_in[0], (float*)d_out,
                                                     rem_start, n);
    }
}